// round 7
// baseline (speedup 1.0000x reference)
#include <cuda_runtime.h>
#include <cstdint>

#define BATCH   65536
#define D0      768
#define D1      512
#define D2      256
#define D3      128
#define NCODES  256
#define NLEVELS 4
#define BETA_F  0.25f
#define QBLOCKS 256

typedef unsigned long long ull;

// ---------------- scratch (no cudaMalloc allowed) ----------------
__device__ float g_h1[(size_t)BATCH * D1];   // 128 MB
__device__ float g_h2[(size_t)BATCH * D2];   //  64 MB
__device__ float g_z [(size_t)BATCH * D3];   //  32 MB
__device__ float g_xq[(size_t)BATCH * D3];   //  32 MB
__device__ float g_loss_part[QBLOCKS];

// packed fp32x2 (quant kernel)
#define PACK2(d, lo, hi) \
    asm("mov.b64 %0, {%1, %2};" : "=l"(d) : "f"(lo), "f"(hi))
#define UNPACK2(lo, hi, v) \
    asm("mov.b64 {%0, %1}, %2;" : "=f"(lo), "=f"(hi) : "l"(v))
#define FMA2(d, a, b) \
    asm("fma.rn.f32x2 %0, %1, %2, %0;" : "+l"(d) : "l"(a), "l"(b))
#define FMA2D(d, a, b, c) \
    asm("fma.rn.f32x2 %0, %1, %2, %3;" : "=l"(d) : "l"(a), "l"(b), "l"(c))

// ---------------- scalar fp32 GEMM, 128x128 tile, reg-prefetch pipeline ----
// BM=BN=128, BK=16, TM=TN=8, 256 threads (16x16).
template <bool RELU>
__global__ __launch_bounds__(256) void sgemm_bias(
    const float* __restrict__ A, const float* __restrict__ W,
    const float* __restrict__ bias, float* __restrict__ C,
    int M, int N, int K)
{
    constexpr int BK = 16;
    __shared__ __align__(16) float As[BK][128];   // [k][m] transposed
    __shared__ __align__(16) float Bs[BK][128];   // [k][n]

    const int tid = threadIdx.x;
    const int tx  = tid & 15;          // N group (x8)
    const int ty  = tid >> 4;          // M group (x8)
    const int rowBase = blockIdx.y * 128;
    const int colBase = blockIdx.x * 128;

    // global-load indices (fixed per thread)
    const int am = tid >> 1;           // A: 128 rows, 2 float4/row/chunk
    const int aq = tid & 1;            //    0..1 (float4 pair -> 8 floats? no: 16 floats/row = 4 float4)
    // A chunk = 128 rows x 16 floats = 512 float4 -> 2 per thread:
    //   idx = tid + t*256 ; m = idx>>2 ; q = idx&3
    const int bk0 = tid >> 5;          // B: 16 rows x 32 float4 = 512 -> 2 per thread
    const int bn0 = tid & 31;

    float acc[8][8];
#pragma unroll
    for (int i = 0; i < 8; i++)
#pragma unroll
        for (int j = 0; j < 8; j++) acc[i][j] = 0.0f;

    float4 pA[2], pB[2];

    auto ldchunk = [&](int k0) {
#pragma unroll
        for (int t = 0; t < 2; t++) {
            int idx = tid + t * 256;
            int m = idx >> 2, q = idx & 3;
            pA[t] = *reinterpret_cast<const float4*>(
                &A[(size_t)(rowBase + m) * K + k0 + q * 4]);
        }
#pragma unroll
        for (int t = 0; t < 2; t++) {
            int idx = tid + t * 256;
            int k = idx >> 5, n4 = idx & 31;
            pB[t] = *reinterpret_cast<const float4*>(
                &W[(size_t)(k0 + k) * N + colBase + n4 * 4]);
        }
    };
    auto stchunk = [&]() {
#pragma unroll
        for (int t = 0; t < 2; t++) {
            int idx = tid + t * 256;
            int m = idx >> 2, q = idx & 3;
            As[q * 4 + 0][m] = pA[t].x;
            As[q * 4 + 1][m] = pA[t].y;
            As[q * 4 + 2][m] = pA[t].z;
            As[q * 4 + 3][m] = pA[t].w;
        }
#pragma unroll
        for (int t = 0; t < 2; t++) {
            int idx = tid + t * 256;
            int k = idx >> 5, n4 = idx & 31;
            *reinterpret_cast<float4*>(&Bs[k][n4 * 4]) = pB[t];
        }
    };

    (void)am; (void)aq; (void)bk0; (void)bn0;

    ldchunk(0);
    for (int k0 = 0; k0 < K; k0 += BK) {
        stchunk();
        __syncthreads();
        if (k0 + BK < K) ldchunk(k0 + BK);

#pragma unroll
        for (int kk = 0; kk < BK; kk++) {
            float4 a0 = *reinterpret_cast<const float4*>(&As[kk][ty * 8]);
            float4 a1 = *reinterpret_cast<const float4*>(&As[kk][ty * 8 + 4]);
            float4 b0 = *reinterpret_cast<const float4*>(&Bs[kk][tx * 8]);
            float4 b1 = *reinterpret_cast<const float4*>(&Bs[kk][tx * 8 + 4]);
            float a[8] = {a0.x, a0.y, a0.z, a0.w, a1.x, a1.y, a1.z, a1.w};
            float b[8] = {b0.x, b0.y, b0.z, b0.w, b1.x, b1.y, b1.z, b1.w};
#pragma unroll
            for (int i = 0; i < 8; i++)
#pragma unroll
                for (int j = 0; j < 8; j++)
                    acc[i][j] += a[i] * b[j];
        }
        __syncthreads();
    }

    float4 bv0 = *reinterpret_cast<const float4*>(&bias[colBase + tx * 8]);
    float4 bv1 = *reinterpret_cast<const float4*>(&bias[colBase + tx * 8 + 4]);
    const float bb[8] = {bv0.x, bv0.y, bv0.z, bv0.w, bv1.x, bv1.y, bv1.z, bv1.w};
#pragma unroll
    for (int i = 0; i < 8; i++) {
        int r = rowBase + ty * 8 + i;
        float o[8];
#pragma unroll
        for (int j = 0; j < 8; j++) {
            o[j] = acc[i][j] + bb[j];
            if (RELU) o[j] = fmaxf(o[j], 0.0f);
        }
        float4* cp = reinterpret_cast<float4*>(&C[(size_t)r * N + colBase + tx * 8]);
        cp[0] = make_float4(o[0], o[1], o[2], o[3]);
        cp[1] = make_float4(o[4], o[5], o[6], o[7]);
    }
}

// ---------------- fused residual quantization (all 4 levels, proven R3) -----
__global__ __launch_bounds__(256) void quant_all(
    const float* __restrict__ z, const float* __restrict__ codebooks,
    float* __restrict__ xq, float* __restrict__ partials)
{
    __shared__ __align__(16) float sC[64 * D3];
    __shared__ float snorm[64];
    __shared__ float sred[256];

    const int tid = threadIdx.x;
    const size_t row = (size_t)blockIdx.x * 256 + tid;

    ull r2[64];
    {
        const ulonglong2* zp = reinterpret_cast<const ulonglong2*>(z + row * D3);
#pragma unroll
        for (int k = 0; k < 32; k++) {
            ulonglong2 v = zp[k];
            r2[2 * k] = v.x; r2[2 * k + 1] = v.y;
        }
    }
    ull mone; PACK2(mone, -1.0f, -1.0f);
    ull ls0 = 0ULL, ls1 = 0ULL;

    for (int l = 0; l < NLEVELS; l++) {
        const float* C = codebooks + (size_t)l * NCODES * D3;
        float best = 3.4e38f;
        int bi = 0;

        for (int ch = 0; ch < 4; ch++) {
            __syncthreads();
            const float4* src =
                reinterpret_cast<const float4*>(C + (size_t)ch * 64 * D3);
            float4* dst = reinterpret_cast<float4*>(sC);
#pragma unroll
            for (int i = 0; i < 8; i++) dst[tid + i * 256] = src[tid + i * 256];
            __syncthreads();
            if (tid < 64) {
                const float4* cp = reinterpret_cast<const float4*>(sC + tid * D3);
                float s = 0.0f;
#pragma unroll
                for (int i = 0; i < 32; i++) {
                    float4 v = cp[i];
                    s += v.x * v.x + v.y * v.y + v.z * v.z + v.w * v.w;
                }
                snorm[tid] = s;
            }
            __syncthreads();

            for (int c = 0; c < 64; c++) {
                const ulonglong2* cp =
                    reinterpret_cast<const ulonglong2*>(sC + c * D3);
                ull a0 = 0ULL, a1 = 0ULL;
#pragma unroll
                for (int k = 0; k < 32; k++) {
                    ulonglong2 v = cp[k];
                    FMA2(a0, r2[2 * k],     v.x);
                    FMA2(a1, r2[2 * k + 1], v.y);
                }
                float s0, s1, s2, s3;
                UNPACK2(s0, s1, a0);
                UNPACK2(s2, s3, a1);
                float dot = (s0 + s1) + (s2 + s3);
                float score = snorm[c] - 2.0f * dot;
                if (score < best) { best = score; bi = ch * 64 + c; }
            }
        }

        const ulonglong2* qp =
            reinterpret_cast<const ulonglong2*>(C + (size_t)bi * D3);
#pragma unroll
        for (int k = 0; k < 32; k++) {
            ulonglong2 q = qp[k];
            ull d0, d1;
            FMA2D(d0, q.x, mone, r2[2 * k]);      // r - q
            FMA2D(d1, q.y, mone, r2[2 * k + 1]);
            FMA2(ls0, d0, d0);
            FMA2(ls1, d1, d1);
            r2[2 * k] = d0; r2[2 * k + 1] = d1;
        }
    }

    {   // x_q = z - r_final
        const ulonglong2* zp = reinterpret_cast<const ulonglong2*>(z + row * D3);
        ulonglong2* xp = reinterpret_cast<ulonglong2*>(xq + row * D3);
#pragma unroll
        for (int k = 0; k < 32; k++) {
            ulonglong2 v = zp[k];
            ulonglong2 o;
            FMA2D(o.x, r2[2 * k],     mone, v.x);
            FMA2D(o.y, r2[2 * k + 1], mone, v.y);
            xp[k] = o;
        }
    }

    float s0, s1, s2, s3;
    UNPACK2(s0, s1, ls0);
    UNPACK2(s2, s3, ls1);
    sred[tid] = (s0 + s1) + (s2 + s3);
    __syncthreads();
#pragma unroll
    for (int s = 128; s > 0; s >>= 1) {
        if (tid < s) sred[tid] += sred[tid + s];
        __syncthreads();
    }
    if (tid == 0) partials[blockIdx.x] = sred[0];
}

__global__ void finalize_loss(const float* __restrict__ partials,
                              float* __restrict__ out)
{
    if (threadIdx.x == 0 && blockIdx.x == 0) {
        float tot = 0.0f;
        for (int i = 0; i < QBLOCKS; i++) tot += partials[i];
        float rq = (1.0f + BETA_F) * tot /
                   ((float)NLEVELS * (float)BATCH * (float)D3);
        *out = rq;
    }
}

// ---------------- launch ----------------
extern "C" void kernel_launch(void* const* d_in, const int* in_sizes, int n_in,
                              void* d_out, int out_size)
{
    (void)in_sizes; (void)n_in;
    const float* x   = (const float*)d_in[0];
    const float* ew0 = (const float*)d_in[1];
    const float* eb0 = (const float*)d_in[2];
    const float* ew1 = (const float*)d_in[3];
    const float* eb1 = (const float*)d_in[4];
    const float* ew2 = (const float*)d_in[5];
    const float* eb2 = (const float*)d_in[6];
    const float* dw0 = (const float*)d_in[7];
    const float* db0 = (const float*)d_in[8];
    const float* dw1 = (const float*)d_in[9];
    const float* db1 = (const float*)d_in[10];
    const float* dw2 = (const float*)d_in[11];
    const float* db2 = (const float*)d_in[12];
    const float* cb  = (const float*)d_in[13];
    float* out = (float*)d_out;

    float *h1, *h2, *z, *xq, *lp;
    cudaGetSymbolAddress((void**)&h1, g_h1);
    cudaGetSymbolAddress((void**)&h2, g_h2);
    cudaGetSymbolAddress((void**)&z,  g_z);
    cudaGetSymbolAddress((void**)&xq, g_xq);
    cudaGetSymbolAddress((void**)&lp, g_loss_part);

    const int MB = BATCH / 128;

    // encoder
    sgemm_bias<true ><<<dim3(D1 / 128, MB), 256>>>(x,  ew0, eb0, h1, BATCH, D1, D0);
    sgemm_bias<true ><<<dim3(D2 / 128, MB), 256>>>(h1, ew1, eb1, h2, BATCH, D2, D1);
    sgemm_bias<false><<<dim3(D3 / 128, MB), 256>>>(h2, ew2, eb2, z,  BATCH, D3, D2);

    // fused residual quantization
    quant_all<<<QBLOCKS, 256>>>(z, cb, xq, lp);

    // decoder (y_q == x_q in forward value)
    sgemm_bias<true ><<<dim3(D2 / 128, MB), 256>>>(xq, dw0, db0, h2,  BATCH, D2, D3);
    sgemm_bias<true ><<<dim3(D1 / 128, MB), 256>>>(h2, dw1, db1, h1,  BATCH, D1, D2);
    sgemm_bias<false><<<dim3(D0 / 128, MB), 256>>>(h1, dw2, db2, out, BATCH, D0, D1);

    finalize_loss<<<1, 32>>>(lp, out + (size_t)out_size - 1);
}

// round 8
// speedup vs baseline: 1.1537x; 1.1537x over previous
#include <cuda_runtime.h>
#include <cstdint>

#define BATCH   65536
#define D0      768
#define D1      512
#define D2      256
#define D3      128
#define NCODES  256
#define NLEVELS 4
#define BETA_F  0.25f
#define QBLOCKS 256

typedef unsigned long long ull;

// ---------------- scratch (no cudaMalloc allowed) ----------------
__device__ float g_h1[(size_t)BATCH * D1];   // 128 MB
__device__ float g_h2[(size_t)BATCH * D2];   //  64 MB
__device__ float g_z [(size_t)BATCH * D3];   //  32 MB
__device__ float g_xq[(size_t)BATCH * D3];   //  32 MB
__device__ float g_loss_part[QBLOCKS];

// packed fp32x2 (quant kernel)
#define PACK2(d, lo, hi) \
    asm("mov.b64 %0, {%1, %2};" : "=l"(d) : "f"(lo), "f"(hi))
#define UNPACK2(lo, hi, v) \
    asm("mov.b64 {%0, %1}, %2;" : "=f"(lo), "=f"(hi) : "l"(v))
#define FMA2(d, a, b) \
    asm("fma.rn.f32x2 %0, %1, %2, %0;" : "+l"(d) : "l"(a), "l"(b))
#define FMA2D(d, a, b, c) \
    asm("fma.rn.f32x2 %0, %1, %2, %3;" : "=l"(d) : "l"(a), "l"(b), "l"(c))

__device__ __forceinline__ uint32_t smem_u32(const void* p) {
    uint32_t a;
    asm("{ .reg .u64 t; cvta.to.shared.u64 t, %1; cvt.u32.u64 %0, t; }"
        : "=r"(a) : "l"(p));
    return a;
}
__device__ __forceinline__ void cpasync16(uint32_t dst, const void* src) {
    asm volatile("cp.async.cg.shared.global [%0], [%1], 16;"
                 :: "r"(dst), "l"(src));
}
__device__ __forceinline__ void cpcommit() {
    asm volatile("cp.async.commit_group;" ::: "memory");
}
template <int N>
__device__ __forceinline__ void cpwait() {
    asm volatile("cp.async.wait_group %0;" :: "n"(N) : "memory");
}

// ---------------- cp.async double-buffered fp32 GEMM ----------------
// BM=128, BN=64, BK=32, TM=8, TN=4, 256 threads.
// A staged row-major [m][k] with pad stride 36 (reads are k-float4, bcast).
#define ASTR 36
#define A_BUF_FLOATS (128 * ASTR)
#define B_BUF_FLOATS (32 * 64)
#define GSMEM_BYTES ((2 * A_BUF_FLOATS + 2 * B_BUF_FLOATS) * 4)

template <bool RELU>
__global__ __launch_bounds__(256) void sgemm_bias(
    const float* __restrict__ A, const float* __restrict__ W,
    const float* __restrict__ bias, float* __restrict__ C,
    int M, int N, int K)
{
    extern __shared__ float smf[];
    float* Asm[2] = {smf, smf + A_BUF_FLOATS};
    float* Bsm[2] = {smf + 2 * A_BUF_FLOATS, smf + 2 * A_BUF_FLOATS + B_BUF_FLOATS};
    const uint32_t aB0 = smem_u32(Asm[0]), aB1 = smem_u32(Asm[1]);
    const uint32_t bB0 = smem_u32(Bsm[0]), bB1 = smem_u32(Bsm[1]);

    const int tid = threadIdx.x;
    const int tx  = tid & 15;          // N group (x4)
    const int ty  = tid >> 4;          // M group (x8)
    const int rowBase = blockIdx.y * 128;
    const int colBase = blockIdx.x * 64;

    float acc[8][4];
#pragma unroll
    for (int i = 0; i < 8; i++)
#pragma unroll
        for (int j = 0; j < 4; j++) acc[i][j] = 0.0f;

    // per-thread cp.async indices
    const int am = tid >> 1;           // unused template helper
    (void)am;

    auto issue_chunk = [&](int k0, int buf) {
        const uint32_t aBase = buf ? aB1 : aB0;
        const uint32_t bBase = buf ? bB1 : bB0;
        // A: 128 rows x 32 floats = 1024 float4, 4 per thread
#pragma unroll
        for (int t = 0; t < 4; t++) {
            int idx = tid + t * 256;
            int m = idx >> 3, q = idx & 7;
            cpasync16(aBase + (uint32_t)(m * ASTR + q * 4) * 4,
                      &A[(size_t)(rowBase + m) * K + k0 + q * 4]);
        }
        // B: 32 rows x 64 floats = 512 float4, 2 per thread
#pragma unroll
        for (int t = 0; t < 2; t++) {
            int idx = tid + t * 256;
            int k = idx >> 4, n4 = idx & 15;
            cpasync16(bBase + (uint32_t)(k * 64 + n4 * 4) * 4,
                      &W[(size_t)(k0 + k) * N + colBase + n4 * 4]);
        }
        cpcommit();
    };

    const int NC = K >> 5;
    issue_chunk(0, 0);

    for (int i = 0; i < NC; i++) {
        const int buf = i & 1;
        if (i + 1 < NC) {
            issue_chunk((i + 1) << 5, buf ^ 1);
            cpwait<1>();
        } else {
            cpwait<0>();
        }
        __syncthreads();

        const float* as = Asm[buf];
        const float* bs = Bsm[buf];
#pragma unroll
        for (int kb = 0; kb < 32; kb += 4) {
            float4 b4[4];
#pragma unroll
            for (int j = 0; j < 4; j++)
                b4[j] = *reinterpret_cast<const float4*>(
                    &bs[(kb + j) * 64 + tx * 4]);
#pragma unroll
            for (int ii = 0; ii < 8; ii++) {
                float4 a4 = *reinterpret_cast<const float4*>(
                    &as[(ty * 8 + ii) * ASTR + kb]);
#pragma unroll
                for (int j = 0; j < 4; j++) {
                    float* aj = &acc[ii][0];
                    aj[j] += a4.x * (&b4[0].x)[j];
                    aj[j] += a4.y * (&b4[1].x)[j];
                    aj[j] += a4.z * (&b4[2].x)[j];
                    aj[j] += a4.w * (&b4[3].x)[j];
                }
            }
        }
        __syncthreads();
    }

    float4 bv = *reinterpret_cast<const float4*>(&bias[colBase + tx * 4]);
    const float bb[4] = {bv.x, bv.y, bv.z, bv.w};
#pragma unroll
    for (int i = 0; i < 8; i++) {
        int r = rowBase + ty * 8 + i;
        float4 o;
        o.x = acc[i][0] + bb[0];
        o.y = acc[i][1] + bb[1];
        o.z = acc[i][2] + bb[2];
        o.w = acc[i][3] + bb[3];
        if (RELU) {
            o.x = fmaxf(o.x, 0.0f); o.y = fmaxf(o.y, 0.0f);
            o.z = fmaxf(o.z, 0.0f); o.w = fmaxf(o.w, 0.0f);
        }
        *reinterpret_cast<float4*>(&C[(size_t)r * N + colBase + tx * 4]) = o;
    }
}

// ---------------- fused residual quantization (all 4 levels, proven R3) -----
__global__ __launch_bounds__(256) void quant_all(
    const float* __restrict__ z, const float* __restrict__ codebooks,
    float* __restrict__ xq, float* __restrict__ partials)
{
    __shared__ __align__(16) float sC[64 * D3];
    __shared__ float snorm[64];
    __shared__ float sred[256];

    const int tid = threadIdx.x;
    const size_t row = (size_t)blockIdx.x * 256 + tid;

    ull r2[64];
    {
        const ulonglong2* zp = reinterpret_cast<const ulonglong2*>(z + row * D3);
#pragma unroll
        for (int k = 0; k < 32; k++) {
            ulonglong2 v = zp[k];
            r2[2 * k] = v.x; r2[2 * k + 1] = v.y;
        }
    }
    ull mone; PACK2(mone, -1.0f, -1.0f);
    ull ls0 = 0ULL, ls1 = 0ULL;

    for (int l = 0; l < NLEVELS; l++) {
        const float* C = codebooks + (size_t)l * NCODES * D3;
        float best = 3.4e38f;
        int bi = 0;

        for (int ch = 0; ch < 4; ch++) {
            __syncthreads();
            const float4* src =
                reinterpret_cast<const float4*>(C + (size_t)ch * 64 * D3);
            float4* dst = reinterpret_cast<float4*>(sC);
#pragma unroll
            for (int i = 0; i < 8; i++) dst[tid + i * 256] = src[tid + i * 256];
            __syncthreads();
            if (tid < 64) {
                const float4* cp = reinterpret_cast<const float4*>(sC + tid * D3);
                float s = 0.0f;
#pragma unroll
                for (int i = 0; i < 32; i++) {
                    float4 v = cp[i];
                    s += v.x * v.x + v.y * v.y + v.z * v.z + v.w * v.w;
                }
                snorm[tid] = s;
            }
            __syncthreads();

            for (int c = 0; c < 64; c++) {
                const ulonglong2* cp =
                    reinterpret_cast<const ulonglong2*>(sC + c * D3);
                ull a0 = 0ULL, a1 = 0ULL;
#pragma unroll
                for (int k = 0; k < 32; k++) {
                    ulonglong2 v = cp[k];
                    FMA2(a0, r2[2 * k],     v.x);
                    FMA2(a1, r2[2 * k + 1], v.y);
                }
                float s0, s1, s2, s3;
                UNPACK2(s0, s1, a0);
                UNPACK2(s2, s3, a1);
                float dot = (s0 + s1) + (s2 + s3);
                float score = snorm[c] - 2.0f * dot;
                if (score < best) { best = score; bi = ch * 64 + c; }
            }
        }

        const ulonglong2* qp =
            reinterpret_cast<const ulonglong2*>(C + (size_t)bi * D3);
#pragma unroll
        for (int k = 0; k < 32; k++) {
            ulonglong2 q = qp[k];
            ull d0, d1;
            FMA2D(d0, q.x, mone, r2[2 * k]);      // r - q
            FMA2D(d1, q.y, mone, r2[2 * k + 1]);
            FMA2(ls0, d0, d0);
            FMA2(ls1, d1, d1);
            r2[2 * k] = d0; r2[2 * k + 1] = d1;
        }
    }

    {   // x_q = z - r_final
        const ulonglong2* zp = reinterpret_cast<const ulonglong2*>(z + row * D3);
        ulonglong2* xp = reinterpret_cast<ulonglong2*>(xq + row * D3);
#pragma unroll
        for (int k = 0; k < 32; k++) {
            ulonglong2 v = zp[k];
            ulonglong2 o;
            FMA2D(o.x, r2[2 * k],     mone, v.x);
            FMA2D(o.y, r2[2 * k + 1], mone, v.y);
            xp[k] = o;
        }
    }

    float s0, s1, s2, s3;
    UNPACK2(s0, s1, ls0);
    UNPACK2(s2, s3, ls1);
    sred[tid] = (s0 + s1) + (s2 + s3);
    __syncthreads();
#pragma unroll
    for (int s = 128; s > 0; s >>= 1) {
        if (tid < s) sred[tid] += sred[tid + s];
        __syncthreads();
    }
    if (tid == 0) partials[blockIdx.x] = sred[0];
}

__global__ void finalize_loss(const float* __restrict__ partials,
                              float* __restrict__ out)
{
    if (threadIdx.x == 0 && blockIdx.x == 0) {
        float tot = 0.0f;
        for (int i = 0; i < QBLOCKS; i++) tot += partials[i];
        float rq = (1.0f + BETA_F) * tot /
                   ((float)NLEVELS * (float)BATCH * (float)D3);
        *out = rq;
    }
}

// ---------------- launch ----------------
extern "C" void kernel_launch(void* const* d_in, const int* in_sizes, int n_in,
                              void* d_out, int out_size)
{
    (void)in_sizes; (void)n_in;
    const float* x   = (const float*)d_in[0];
    const float* ew0 = (const float*)d_in[1];
    const float* eb0 = (const float*)d_in[2];
    const float* ew1 = (const float*)d_in[3];
    const float* eb1 = (const float*)d_in[4];
    const float* ew2 = (const float*)d_in[5];
    const float* eb2 = (const float*)d_in[6];
    const float* dw0 = (const float*)d_in[7];
    const float* db0 = (const float*)d_in[8];
    const float* dw1 = (const float*)d_in[9];
    const float* db1 = (const float*)d_in[10];
    const float* dw2 = (const float*)d_in[11];
    const float* db2 = (const float*)d_in[12];
    const float* cb  = (const float*)d_in[13];
    float* out = (float*)d_out;

    float *h1, *h2, *z, *xq, *lp;
    cudaGetSymbolAddress((void**)&h1, g_h1);
    cudaGetSymbolAddress((void**)&h2, g_h2);
    cudaGetSymbolAddress((void**)&z,  g_z);
    cudaGetSymbolAddress((void**)&xq, g_xq);
    cudaGetSymbolAddress((void**)&lp, g_loss_part);

    cudaFuncSetAttribute(sgemm_bias<true>,
        cudaFuncAttributeMaxDynamicSharedMemorySize, GSMEM_BYTES);
    cudaFuncSetAttribute(sgemm_bias<false>,
        cudaFuncAttributeMaxDynamicSharedMemorySize, GSMEM_BYTES);

    const int MB = BATCH / 128;

    // encoder
    sgemm_bias<true ><<<dim3(D1 / 64, MB), 256, GSMEM_BYTES>>>(x,  ew0, eb0, h1, BATCH, D1, D0);
    sgemm_bias<true ><<<dim3(D2 / 64, MB), 256, GSMEM_BYTES>>>(h1, ew1, eb1, h2, BATCH, D2, D1);
    sgemm_bias<false><<<dim3(D3 / 64, MB), 256, GSMEM_BYTES>>>(h2, ew2, eb2, z,  BATCH, D3, D2);

    // fused residual quantization
    quant_all<<<QBLOCKS, 256>>>(z, cb, xq, lp);

    // decoder (y_q == x_q in forward value)
    sgemm_bias<true ><<<dim3(D2 / 64, MB), 256, GSMEM_BYTES>>>(xq, dw0, db0, h2,  BATCH, D2, D3);
    sgemm_bias<true ><<<dim3(D1 / 64, MB), 256, GSMEM_BYTES>>>(h2, dw1, db1, h1,  BATCH, D1, D2);
    sgemm_bias<false><<<dim3(D0 / 64, MB), 256, GSMEM_BYTES>>>(h1, dw2, db2, out, BATCH, D0, D1);

    finalize_loss<<<1, 32>>>(lp, out + (size_t)out_size - 1);
}